// round 13
// baseline (speedup 1.0000x reference)
#include <cuda_runtime.h>
#include <cuda_bf16.h>
#include <math.h>

// ---------------- constants ----------------
#define BBATCH 16
#define DIMC  128
#define HDC   64
#define LLC   3136      // 56*56
#define NTOK  49
#define DI_   128
#define DST_  16
#define KDIR  4
#define CX    36
#define HID4  512

// ---------------- scratch ----------------
__device__ float g_pool[BBATCH*DIMC];
__device__ float g_sse [BBATCH*DIMC];
// bf16 activations / intermediates
__device__ __nv_bfloat16 g_xn1bf [(size_t)BBATCH*HDC*LLC];
__device__ __nv_bfloat16 g_xn64bf[(size_t)BBATCH*HDC*LLC];
__device__ __nv_bfloat16 g_qkvbf [(size_t)BBATCH*192*LLC];
__device__ __nv_bfloat16 g_attnobf[(size_t)BBATCH*HDC*LLC];
__device__ __nv_bfloat16 g_tmpbf [(size_t)BBATCH*DI_*LLC];
__device__ __nv_bfloat16 g_xmbf  [(size_t)BBATCH*DI_*LLC];
__device__ __nv_bfloat16 g_xmTbf [(size_t)BBATCH*DI_*LLC];
__device__ __nv_bfloat16 g_pjbf  [(size_t)BBATCH*KDIR*CX*LLC];
__device__ __nv_bfloat16 g_pjTbf [(size_t)BBATCH*2*CX*LLC];
__device__ __nv_bfloat16 g_ysbf  [(size_t)BBATCH*KDIR*DI_*LLC];
__device__ __nv_bfloat16 g_ymgbf [(size_t)BBATCH*DI_*LLC];
__device__ __nv_bfloat16 g_ybf   [(size_t)BBATCH*DIMC*LLC];
__device__ __nv_bfloat16 g_xnbf  [(size_t)BBATCH*DIMC*LLC];
// bf16 weights
__device__ __nv_bfloat16 g_w1bf[HID4*DIMC];
__device__ __nv_bfloat16 g_w2bf[DIMC*HID4];
__device__ __nv_bfloat16 g_wqkvbf[192*HDC];
__device__ __nv_bfloat16 g_wprojbf[HDC*HDC];
__device__ __nv_bfloat16 g_winbf[DI_*HDC];
__device__ __nv_bfloat16 g_wxbf[192*DI_];     // 144 real rows, zero-padded
__device__ __nv_bfloat16 g_woutbf[HDC*DI_];

// ---------------- helpers ----------------
__device__ __forceinline__ float fgelu(float x){
    float u = 0.7978845608028654f*(x + 0.044715f*x*x*x);
    float t;
    asm("tanh.approx.f32 %0, %1;" : "=f"(t) : "f"(u));
    return 0.5f*x*(1.f+t);
}
__device__ __forceinline__ float fsilu(float x){
    return x * (1.f/(1.f+__expf(-x)));
}

// ---------------- 0. weight prep ----------------
__global__ void wprep_kernel(const float* __restrict__ w1, const float* __restrict__ w2,
    const float* __restrict__ xp,
    const float* __restrict__ wq, const float* __restrict__ wk, const float* __restrict__ wv,
    const float* __restrict__ gq, const float* __restrict__ gk, const float* __restrict__ gv,
    const float* __restrict__ wproj, const float* __restrict__ m_in_w,
    const float* __restrict__ m_outw)
{
    int i = blockIdx.x*256 + threadIdx.x;
    if (i < HID4*DIMC) g_w1bf[i] = __float2bfloat16(w1[i]);
    if (i < DIMC*HID4) g_w2bf[i] = __float2bfloat16(w2[i]);
    if (i < 192*DI_){
        if (i < KDIR*CX*DI_){
            int o = i >> 7, d = i & 127;
            int k = o / CX, c = o - k*CX;
            g_wxbf[i] = __float2bfloat16(xp[(k*DI_ + d)*CX + c]);
        } else {
            g_wxbf[i] = __float2bfloat16(0.f);
        }
    }
    if (i < 192*HDC){
        int o = i >> 6, c = i & 63;
        float v;
        if (o < 64)       v = wq[o*64 + c]*gq[c];
        else if (o < 128) v = wk[(o-64)*64 + c]*gk[c];
        else              v = wv[(o-128)*64 + c]*gv[c];
        g_wqkvbf[i] = __float2bfloat16(v);
    }
    if (i < HDC*HDC)  g_wprojbf[i] = __float2bfloat16(wproj[i]);
    if (i < DI_*HDC)  g_winbf[i]   = __float2bfloat16(m_in_w[i]);
    if (i < HDC*DI_)  g_woutbf[i]  = __float2bfloat16(m_outw[i]);
}

// ---------------- 1. fused rms for both halves -> bf16 ----------------
__global__ void rms1_kernel(const float* __restrict__ x, const float* __restrict__ gvm)
{
    __shared__ float ssum[256];
    int tid = threadIdx.x;
    int g = tid >> 6, px = tid & 63;
    int gp = blockIdx.x*64 + px;
    int b = gp / LLC, p = gp - b*LLC;
    const float* xb = x + ((size_t)b*DIMC + g*32)*LLC + p;
    float v[32];
    float s = 0.f;
    #pragma unroll
    for (int i = 0; i < 32; i++){ v[i] = xb[(size_t)i*LLC]; s += v[i]*v[i]; }
    ssum[tid] = s;
    __syncthreads();
    float tot = (g < 2) ? (ssum[px] + ssum[64+px]) : (ssum[128+px] + ssum[192+px]);
    float inv = rsqrtf(tot*(1.f/64.f) + 1e-5f);
    if (g < 2){
        __nv_bfloat16* ob = g_xn1bf + ((size_t)b*HDC + g*32)*LLC + p;
        #pragma unroll
        for (int i = 0; i < 32; i++) ob[(size_t)i*LLC] = __float2bfloat16(v[i]*inv);
    } else {
        int c0 = (g-2)*32;
        __nv_bfloat16* ob = g_xn64bf + ((size_t)b*HDC + c0)*LLC + p;
        #pragma unroll
        for (int i = 0; i < 32; i++) ob[(size_t)i*LLC] = __float2bfloat16(v[i]*inv*gvm[c0+i]);
    }
}

// ---------------- generic bf16 tensor-core GEMM (bf16 out) ----------------
template<int K>
__global__ __launch_bounds__(256) void mma_gemm_kernel(
    const __nv_bfloat16* __restrict__ W, const __nv_bfloat16* __restrict__ X,
    __nv_bfloat16* __restrict__ OUT, const float* __restrict__ bias,
    int Mtot, int ostride, int o_off)
{
    __shared__ __nv_bfloat16 As[64*40];
    __shared__ __nv_bfloat16 Bs[32*136];
    int tid = threadIdx.x;
    int lane = tid & 31, wid = tid >> 5;
    int wm = wid >> 2, wn = wid & 3;
    int p0 = blockIdx.x*128;
    int m0 = blockIdx.y*64;
    int bz = blockIdx.z;

    float acc[2][4][4];
    #pragma unroll
    for (int i = 0; i < 2; i++)
        #pragma unroll
        for (int j = 0; j < 4; j++)
            #pragma unroll
            for (int q = 0; q < 4; q++) acc[i][j][q] = 0.f;

    for (int kc = 0; kc < K; kc += 32){
        __syncthreads();
        {
            int row = tid >> 2, seg = tid & 3;
            uint4 v = *(const uint4*)(W + (size_t)(m0 + row)*K + kc + seg*8);
            *(uint4*)(&As[row*40 + seg*8]) = v;
        }
        {
            int kk = tid >> 3, pg = tid & 7;
            const __nv_bfloat16* src = X + ((size_t)bz*K + kc + kk)*LLC + p0 + pg*16;
            #pragma unroll
            for (int r = 0; r < 2; r++){
                int p = p0 + pg*16 + r*8;
                uint4 v = make_uint4(0u,0u,0u,0u);
                if (p < LLC) v = *(const uint4*)(src + r*8);
                *(uint4*)(&Bs[kk*136 + pg*16 + r*8]) = v;
            }
        }
        __syncthreads();
        #pragma unroll
        for (int ks = 0; ks < 2; ks++){
            int kk16 = ks*16;
            unsigned a[2][4], bfr[4][2];
            const unsigned* As32 = (const unsigned*)As;
            #pragma unroll
            for (int fm = 0; fm < 2; fm++){
                int row = wm*32 + fm*16 + (lane >> 2);
                int c = (kk16 >> 1) + (lane & 3);
                a[fm][0] = As32[row*20 + c];
                a[fm][1] = As32[(row+8)*20 + c];
                a[fm][2] = As32[row*20 + c + 4];
                a[fm][3] = As32[(row+8)*20 + c + 4];
            }
            const unsigned short* Bu = (const unsigned short*)Bs;
            #pragma unroll
            for (int fn = 0; fn < 4; fn++){
                int col = wn*32 + fn*8 + (lane >> 2);
                int kb = kk16 + (lane & 3)*2;
                unsigned lo0 = Bu[kb*136 + col],     hi0 = Bu[(kb+1)*136 + col];
                unsigned lo1 = Bu[(kb+8)*136 + col], hi1 = Bu[(kb+9)*136 + col];
                bfr[fn][0] = lo0 | (hi0 << 16);
                bfr[fn][1] = lo1 | (hi1 << 16);
            }
            #pragma unroll
            for (int fm = 0; fm < 2; fm++)
                #pragma unroll
                for (int fn = 0; fn < 4; fn++){
                    asm volatile(
                        "mma.sync.aligned.m16n8k16.row.col.f32.bf16.bf16.f32 "
                        "{%0,%1,%2,%3}, {%4,%5,%6,%7}, {%8,%9}, {%0,%1,%2,%3};"
                        : "+f"(acc[fm][fn][0]), "+f"(acc[fm][fn][1]),
                          "+f"(acc[fm][fn][2]), "+f"(acc[fm][fn][3])
                        : "r"(a[fm][0]), "r"(a[fm][1]), "r"(a[fm][2]), "r"(a[fm][3]),
                          "r"(bfr[fn][0]), "r"(bfr[fn][1]));
                }
        }
    }

    int r = lane >> 2, c2 = (lane & 3)*2;
    #pragma unroll
    for (int fm = 0; fm < 2; fm++){
        int m = m0 + wm*32 + fm*16 + r;
        #pragma unroll
        for (int fn = 0; fn < 4; fn++){
            int p = p0 + wn*32 + fn*8 + c2;
            if (p < LLC){
                #pragma unroll
                for (int half = 0; half < 2; half++){
                    int mm = m + half*8;
                    if (mm < Mtot){
                        float bv = bias ? bias[mm] : 0.f;
                        float v0 = acc[fm][fn][half*2+0] + bv;
                        float v1 = acc[fm][fn][half*2+1] + bv;
                        size_t off = ((size_t)bz*ostride + o_off + mm)*LLC + p;
                        __nv_bfloat162 h2;
                        h2.x = __float2bfloat16(v0);
                        h2.y = __float2bfloat16(v1);
                        *(__nv_bfloat162*)&OUT[off] = h2;
                    }
                }
            }
        }
    }
}

// ---------------- 2. window-attention core: bf16x2 math, single-pass softmax ----------------
__global__ __launch_bounds__(256, 3) void attncore_kernel(void)
{
    __shared__ __nv_bfloat16 q_s[8*49*8];
    __shared__ __nv_bfloat16 k_s[8*49*8];
    __shared__ __nv_bfloat16 v_s[8*49*8];
    int tid = threadIdx.x, lane = tid & 31, h = tid >> 5;
    int bw = blockIdx.x;
    int b = bw >> 6, wh = (bw >> 3) & 7, wwi = bw & 7;
    int pbase = (wh*7)*56 + wwi*7;
    const __nv_bfloat16* qb = g_qkvbf + ((size_t)b*192 + h*8)*LLC;

    for (int it = lane; it < 392; it += 32){
        int dd = it / 49, j = it - dd*49;
        int pix = pbase + (j/7)*56 + (j - (j/7)*7);
        size_t base = (size_t)dd*LLC + pix;
        float qv = __bfloat162float(qb[base]) * 0.35355339059327373f;
        q_s[(h*49+j)*8+dd] = __float2bfloat16(qv);
        k_s[(h*49+j)*8+dd] = qb[64*LLC + base];
        v_s[(h*49+j)*8+dd] = qb[128*LLC + base];
    }
    __syncwarp();

    __nv_bfloat16* ob = g_attnobf + (size_t)b*HDC*LLC;
    #pragma unroll
    for (int rr = 0; rr < 2; rr++){
        int r = lane + rr*32;
        if (r < 49){
            uint4 qr = *(const uint4*)&q_s[(h*49+r)*8];
            const __nv_bfloat162* q2 = (const __nv_bfloat162*)&qr;
            float sum = 0.f;
            __nv_bfloat162 o2[4];
            __nv_bfloat162 zz = __float2bfloat162_rn(0.f);
            o2[0] = zz; o2[1] = zz; o2[2] = zz; o2[3] = zz;
            #pragma unroll 7
            for (int j = 0; j < 49; j++){
                uint4 kr = *(const uint4*)&k_s[(h*49+j)*8];
                const __nv_bfloat162* k2 = (const __nv_bfloat162*)&kr;
                __nv_bfloat162 a2 = __hmul2(q2[0], k2[0]);
                a2 = __hfma2(q2[1], k2[1], a2);
                a2 = __hfma2(q2[2], k2[2], a2);
                a2 = __hfma2(q2[3], k2[3], a2);
                float s = __bfloat162float(a2.x) + __bfloat162float(a2.y);
                float e = __expf(s);
                sum += e;
                __nv_bfloat162 e2 = __float2bfloat162_rn(e);
                uint4 vr = *(const uint4*)&v_s[(h*49+j)*8];
                const __nv_bfloat162* v2 = (const __nv_bfloat162*)&vr;
                o2[0] = __hfma2(e2, v2[0], o2[0]);
                o2[1] = __hfma2(e2, v2[1], o2[1]);
                o2[2] = __hfma2(e2, v2[2], o2[2]);
                o2[3] = __hfma2(e2, v2[3], o2[3]);
            }
            float rinv = 1.f/sum;
            int pr = pbase + (r/7)*56 + (r - (r/7)*7);
            #pragma unroll
            for (int g2i = 0; g2i < 4; g2i++){
                ob[(size_t)(h*8+g2i*2+0)*LLC + pr] =
                    __float2bfloat16(__bfloat162float(o2[g2i].x)*rinv);
                ob[(size_t)(h*8+g2i*2+1)*LLC + pr] =
                    __float2bfloat16(__bfloat162float(o2[g2i].y)*rinv);
            }
        }
    }
}

// ---------------- 3. fused depthwise 3x3 + silu -> bf16 (natural + transposed) ----------------
__global__ __launch_bounds__(256) void dwconvT_kernel(const float* __restrict__ cw,
                                                      const float* __restrict__ cb)
{
    __shared__ float in_s[58*58];
    __shared__ float out_s[56*57 + 8];
    int tid = threadIdx.x;
    int bc = blockIdx.x;
    int c = bc & (DI_-1);
    const __nv_bfloat16* src = g_tmpbf + (size_t)bc*LLC;
    float wc[9];
    #pragma unroll
    for (int i = 0; i < 9; i++) wc[i] = cw[c*9 + i];
    float bcv = cb[c];

    for (int i = tid; i < 58*58; i += 256){
        int row = i / 58, col = i - row*58;
        int hy = row - 1, wx = col - 1;
        float v = 0.f;
        if (hy >= 0 && hy < 56 && wx >= 0 && wx < 56) v = __bfloat162float(src[hy*56 + wx]);
        in_s[i] = v;
    }
    __syncthreads();
    __nv_bfloat16* db = g_xmbf + (size_t)bc*LLC;
    for (int p = tid; p < LLC; p += 256){
        int h = p / 56, w = p - h*56;
        const float* ip = &in_s[h*58 + w];
        float acc = bcv;
        acc = fmaf(ip[0],     wc[0], acc);
        acc = fmaf(ip[1],     wc[1], acc);
        acc = fmaf(ip[2],     wc[2], acc);
        acc = fmaf(ip[58],    wc[3], acc);
        acc = fmaf(ip[59],    wc[4], acc);
        acc = fmaf(ip[60],    wc[5], acc);
        acc = fmaf(ip[116],   wc[6], acc);
        acc = fmaf(ip[117],   wc[7], acc);
        acc = fmaf(ip[118],   wc[8], acc);
        float val = fsilu(acc);
        db[p] = __float2bfloat16(val);
        out_s[h*57 + w] = val;
    }
    __syncthreads();
    __nv_bfloat16* dt = g_xmTbf + (size_t)bc*LLC;
    for (int i = tid; i < LLC; i += 256){
        int hh = i / 56, ww = i - hh*56;
        dt[i] = __float2bfloat16(out_s[ww*57 + hh]);
    }
}

// ---------------- 4. transpose pj(k1,k3) slices (bf16) ----------------
__global__ void transposePJ_kernel(void)
{
    __shared__ float sm[56*57 + 8];
    int j = blockIdx.x;
    int b = j / (2*CX), r = j - b*(2*CX);
    int kk = (r < CX) ? 1 : 3;
    int c = (r < CX) ? r : r - CX;
    const __nv_bfloat16* src = g_pjbf + ((size_t)b*KDIR*CX + kk*CX + c)*LLC;
    __nv_bfloat16* dst = g_pjTbf + (size_t)j*LLC;
    int tid = threadIdx.x;
    for (int i = tid; i < LLC; i += 256){
        int hh = i/56, ww = i - hh*56;
        sm[hh*57 + ww] = __bfloat162float(src[i]);
    }
    __syncthreads();
    for (int i = tid; i < LLC; i += 256){
        int hh = i/56, ww = i - hh*56;
        dst[i] = __float2bfloat16(sm[ww*57 + hh]);
    }
}

// ---------------- 5. selective scan: no shfl in serial loop, bf162 loads ----------------
// grid 256 = (b*4+k)*4+q, block 128 = 32 ch x 4 subs; dynamic smem 69KB
__global__ __launch_bounds__(128) void scan_kernel(const float* __restrict__ dtw,
    const float* __restrict__ dtb, const float* __restrict__ alog, const float* __restrict__ Dp)
{
    extern __shared__ float ssm[];
    float* dts  = ssm;              // 4*64
    float* Uc   = dts + 256;        // 32*65 (u, then u*D after phase A)
    float* du_s = Uc + 2080;        // 32*65
    float* p1_s = du_s + 2080;      // 32*65
    float* Pt   = p1_s + 2080;      // 64*40
    float* Yp   = Pt + 2560;        // 64*128: [t][ch*4+sub]
    __shared__ float dtw4s[32][4];
    __shared__ float dtbs[32], Dds[32];

    int tid = threadIdx.x;
    int blk = blockIdx.x;
    int q = blk & 3;
    int k = (blk >> 2) & 3;
    int b = blk >> 4;
    int ch = tid >> 2;
    int sub = tid & 3;
    int ng = sub*4;
    int d = q*32 + ch;
    int kd = k*DI_ + d;

    if (tid < 32){
        int kdl = k*DI_ + q*32 + tid;
        dtbs[tid] = dtb[kdl];
        Dds[tid]  = Dp[kdl];
        #pragma unroll
        for (int r = 0; r < 4; r++) dtw4s[tid][r] = dtw[kdl*4 + r];
    }
    float A2[4];
    bool structured = true;
    #pragma unroll
    for (int n = 0; n < 4; n++){
        A2[n] = -__expf(alog[kd*DST_ + ng + n]);
        if (fabsf(A2[n] + (float)(ng + n + 1)) > 1e-3f) structured = false;
    }
    float hst[4] = {0.f, 0.f, 0.f, 0.f};

    bool fwd = (k < 2);
    const __nv_bfloat16* usrc = ((k == 0) || (k == 2))
        ? (g_xmbf  + ((size_t)b*DI_ + q*32)*LLC)
        : (g_xmTbf + ((size_t)b*DI_ + q*32)*LLC);
    const __nv_bfloat16* psrc;
    if (k == 0)      psrc = g_pjbf + ((size_t)b*KDIR*CX + 0*CX)*LLC;
    else if (k == 2) psrc = g_pjbf + ((size_t)b*KDIR*CX + 2*CX)*LLC;
    else if (k == 1) psrc = g_pjTbf + ((size_t)b*2*CX)*LLC;
    else             psrc = g_pjTbf + ((size_t)b*2*CX + CX)*LLC;
    __nv_bfloat16* yb = g_ysbf + (((size_t)(b*KDIR + k))*DI_ + q*32)*LLC;
    __syncthreads();

    for (int s0 = 0; s0 < LLC; s0 += 64){
        // ---- staged loads (bf162 pairs) ----
        #pragma unroll
        for (int rr = 0; rr < 8; rr++){
            int pi = tid + rr*128;              // 1024 pairs: Uc
            int cc = pi >> 5, tp = (pi & 31)*2;
            __nv_bfloat162 v;
            if (fwd) v = *(const __nv_bfloat162*)(usrc + (size_t)cc*LLC + s0 + tp);
            else {
                v = *(const __nv_bfloat162*)(usrc + (size_t)cc*LLC + (LLC-2-s0-tp));
                __nv_bfloat16 tmp = v.x; v.x = v.y; v.y = tmp;
            }
            Uc[cc*65 + tp]     = __bfloat162float(v.x);
            Uc[cc*65 + tp + 1] = __bfloat162float(v.y);
        }
        {   // dt rows: 128 pairs
            int pi = tid;
            int r = pi >> 5, tp = (pi & 31)*2;
            __nv_bfloat162 v;
            if (fwd) v = *(const __nv_bfloat162*)(psrc + (size_t)r*LLC + s0 + tp);
            else {
                v = *(const __nv_bfloat162*)(psrc + (size_t)r*LLC + (LLC-2-s0-tp));
                __nv_bfloat16 tmp = v.x; v.x = v.y; v.y = tmp;
            }
            dts[r*64 + tp]     = __bfloat162float(v.x);
            dts[r*64 + tp + 1] = __bfloat162float(v.y);
        }
        #pragma unroll
        for (int rr = 0; rr < 8; rr++){
            int pi = tid + rr*128;              // 1024 pairs: B/C rows
            int cc = pi >> 5, tp = (pi & 31)*2;
            __nv_bfloat162 v;
            if (fwd) v = *(const __nv_bfloat162*)(psrc + (size_t)(4+cc)*LLC + s0 + tp);
            else {
                v = *(const __nv_bfloat162*)(psrc + (size_t)(4+cc)*LLC + (LLC-2-s0-tp));
                __nv_bfloat16 tmp = v.x; v.x = v.y; v.y = tmp;
            }
            Pt[tp*40 + cc]     = __bfloat162float(v.x);
            Pt[(tp+1)*40 + cc] = __bfloat162float(v.y);
        }
        __syncthreads();
        // ---- phase A: delta/du/p1; Uc becomes u*D in place ----
        #pragma unroll
        for (int rr = 0; rr < 16; rr++){
            int i = tid + rr*128;
            int cc = i >> 6, t = i & 63;
            float dtr = dtbs[cc];
            dtr = fmaf(dts[t],       dtw4s[cc][0], dtr);
            dtr = fmaf(dts[64 + t],  dtw4s[cc][1], dtr);
            dtr = fmaf(dts[128 + t], dtw4s[cc][2], dtr);
            dtr = fmaf(dts[192 + t], dtw4s[cc][3], dtr);
            float e = __expf(dtr);
            float delta = (dtr > 20.f) ? dtr : __logf(1.f + e);
            float u = Uc[cc*65 + t];
            du_s[cc*65 + t] = delta * u;
            p1_s[cc*65 + t] = __expf(-delta);
            Uc[cc*65 + t] = u * Dds[cc];
        }
        __syncthreads();
        // ---- serial scan over 64 steps (no shfl; partial y to Yp) ----
        #pragma unroll 2
        for (int t = 0; t < 64; t++){
            float du = du_s[ch*65 + t];
            float p1 = p1_s[ch*65 + t];
            float4 Bv = *(const float4*)&Pt[t*40 + ng];
            float4 Cv = *(const float4*)&Pt[t*40 + 16 + ng];
            float pe0, pe1, pe2, pe3;
            if (structured){
                float p2 = p1*p1;
                float p4 = p2*p2;
                float p8 = p4*p4;
                float base = p1;
                if (sub & 1) base *= p4;
                if (sub & 2) base *= p8;
                pe0 = base;
                pe1 = base*p1;
                pe2 = base*p2;
                pe3 = pe2*p1;
            } else {
                pe0 = __powf(p1, -A2[0]);
                pe1 = __powf(p1, -A2[1]);
                pe2 = __powf(p1, -A2[2]);
                pe3 = __powf(p1, -A2[3]);
            }
            hst[0] = fmaf(pe0, hst[0], du*Bv.x);
            hst[1] = fmaf(pe1, hst[1], du*Bv.y);
            hst[2] = fmaf(pe2, hst[2], du*Bv.z);
            hst[3] = fmaf(pe3, hst[3], du*Bv.w);
            float y = hst[0]*Cv.x;
            y = fmaf(hst[1], Cv.y, y);
            y = fmaf(hst[2], Cv.z, y);
            y = fmaf(hst[3], Cv.w, y);
            Yp[t*128 + tid] = y;
        }
        __syncthreads();
        // ---- store: reduce 4 partials + u*D ----
        #pragma unroll
        for (int rr = 0; rr < 16; rr++){
            int i = tid + rr*128;
            int cc = i >> 6, t = i & 63;
            float4 yp = *(const float4*)&Yp[t*128 + cc*4];
            float y = (yp.x + yp.y) + (yp.z + yp.w) + Uc[cc*65 + t];
            yb[(size_t)cc*LLC + s0 + t] = __float2bfloat16(y);
        }
        __syncthreads();
    }
}

// ---------------- 6. cross_merge + gelu -> bf16 ----------------
__global__ void mergegelu_kernel(void)
{
    __shared__ float sm1[56*57 + 8];
    __shared__ float sm3[56*57 + 8];
    int tid = threadIdx.x;
    int dch = blockIdx.x;
    int b   = blockIdx.y;
    const __nv_bfloat16* y0p = g_ysbf + (((size_t)(b*KDIR + 0))*DI_ + dch)*LLC;
    const __nv_bfloat16* y1p = g_ysbf + (((size_t)(b*KDIR + 1))*DI_ + dch)*LLC;
    const __nv_bfloat16* y2p = g_ysbf + (((size_t)(b*KDIR + 2))*DI_ + dch)*LLC;
    const __nv_bfloat16* y3p = g_ysbf + (((size_t)(b*KDIR + 3))*DI_ + dch)*LLC;
    for (int i = tid; i < LLC; i += 256){
        int hh = i / 56, ww = i - hh*56;
        sm1[hh*57 + ww] = __bfloat162float(y1p[i]);
        sm3[hh*57 + ww] = __bfloat162float(y3p[i]);
    }
    __syncthreads();
    __nv_bfloat16* op = g_ymgbf + ((size_t)b*DI_ + dch)*LLC;
    for (int p = tid; p < LLC; p += 256){
        int hh = p / 56, ww = p - hh*56;
        float v = __bfloat162float(y0p[p]) + __bfloat162float(y2p[LLC-1-p])
                + sm1[ww*57 + hh] + sm3[(55-ww)*57 + (55-hh)];
        op[p] = __float2bfloat16(fgelu(v));
    }
}

// ---------------- 7. pool / SE ----------------
__global__ void pool_kernel(void)
{
    __shared__ float red[256];
    int bc = blockIdx.x;
    const __nv_bfloat16* yb = g_ybf + (size_t)bc*LLC;
    float s = 0.f;
    for (int i = threadIdx.x; i < LLC; i += 256) s += __bfloat162float(yb[i]);
    red[threadIdx.x] = s;
    __syncthreads();
    for (int st = 128; st > 0; st >>= 1){
        if (threadIdx.x < st) red[threadIdx.x] += red[threadIdx.x + st];
        __syncthreads();
    }
    if (threadIdx.x == 0) g_pool[bc] = red[0]*(1.f/LLC);
}

__global__ void se_kernel(const float* __restrict__ w1, const float* __restrict__ b1,
    const float* __restrict__ w2, const float* __restrict__ b2)
{
    __shared__ float pv[DIMC];
    __shared__ float h1[32];
    int tid = threadIdx.x;
    int b = blockIdx.x;
    if (tid < DIMC) pv[tid] = g_pool[b*DIMC + tid];
    __syncthreads();
    if (tid < 32){
        float acc = b1[tid];
        #pragma unroll
        for (int c = 0; c < DIMC; c++) acc = fmaf(pv[c], w1[tid*DIMC + c], acc);
        h1[tid] = fmaxf(acc, 0.f);
    }
    __syncthreads();
    if (tid < DIMC){
        float acc = b2[tid];
        #pragma unroll
        for (int j = 0; j < 32; j++) acc = fmaf(h1[j], w2[tid*32 + j], acc);
        g_sse[b*DIMC + tid] = 1.f/(1.f + __expf(-acc));
    }
}

// ---------------- 8. residual1 + rms2d -> bf16 (xn only) ----------------
__global__ void residrms_kernel(const float* __restrict__ x,
    const float* __restrict__ gamma1, const float* __restrict__ gmlp)
{
    __shared__ float ssum[256];
    __shared__ float sg[DIMC];
    int tid = threadIdx.x;
    int g = tid >> 6, px = tid & 63;
    int b = (blockIdx.x*64) / LLC;
    int p = blockIdx.x*64 - b*LLC + px;
    if (tid < DIMC) sg[tid] = gamma1[tid]*g_sse[b*DIMC + tid];
    __syncthreads();
    const float* xb = x + ((size_t)b*DIMC + g*32)*LLC + p;
    const __nv_bfloat16* yb = g_ybf + ((size_t)b*DIMC + g*32)*LLC + p;
    float v[32];
    float s = 0.f;
    #pragma unroll
    for (int i = 0; i < 32; i++){
        float val = fmaf(sg[g*32+i], __bfloat162float(yb[(size_t)i*LLC]), xb[(size_t)i*LLC]);
        v[i] = val;
        s += val*val;
    }
    ssum[tid] = s;
    __syncthreads();
    float tot = ssum[px] + ssum[64+px] + ssum[128+px] + ssum[192+px];
    float inv = rsqrtf(tot*(1.f/DIMC) + 1e-5f);
    __nv_bfloat16* ob = g_xnbf + ((size_t)b*DIMC + g*32)*LLC + p;
    #pragma unroll
    for (int i = 0; i < 32; i++)
        ob[(size_t)i*LLC] = __float2bfloat16(v[i]*inv*gmlp[g*32+i]);
}

// ---------------- 9. fully fused MLP ----------------
__global__ __launch_bounds__(256) void mma_mlpfused_kernel(
    const float* __restrict__ b1v, const float* __restrict__ b2v,
    const float* __restrict__ gamma1, const float* __restrict__ gamma2,
    const float* __restrict__ x, float* __restrict__ outf)
{
    extern __shared__ __nv_bfloat16 smx[];
    __nv_bfloat16* Xs  = smx;
    __nv_bfloat16* Hs  = Xs + 128*136;
    __nv_bfloat16* As1 = Hs + 64*136;
    __nv_bfloat16* As2 = As1 + 64*136;
    int tid = threadIdx.x;
    int lane = tid & 31, wid = tid >> 5;
    int wm = wid >> 2, wn = wid & 3;
    int p0 = blockIdx.x*128;
    int bz = blockIdx.y;

    {
        const __nv_bfloat16* src = g_xnbf + (size_t)bz*DIMC*LLC;
        #pragma unroll
        for (int r = 0; r < 8; r++){
            int i = tid + r*256;
            int row = i >> 4, pg = i & 15;
            int p = p0 + pg*8;
            uint4 v = make_uint4(0u,0u,0u,0u);
            if (p < LLC) v = *(const uint4*)(src + (size_t)row*LLC + p);
            *(uint4*)&Xs[row*136 + pg*8] = v;
        }
    }

    float oacc[4][4][4];
    #pragma unroll
    for (int i = 0; i < 4; i++)
        #pragma unroll
        for (int j = 0; j < 4; j++)
            #pragma unroll
            for (int q = 0; q < 4; q++) oacc[i][j][q] = 0.f;
    __syncthreads();

    for (int mc = 0; mc < 8; mc++){
        #pragma unroll
        for (int r = 0; r < 4; r++){
            int i = tid + r*256;
            int row = i >> 4, pg = i & 15;
            *(uint4*)&As1[row*136 + pg*8] =
                *(const uint4*)(g_w1bf + (size_t)(mc*64 + row)*DIMC + pg*8);
        }
        __syncthreads();

        float acc[2][4][4];
        #pragma unroll
        for (int i = 0; i < 2; i++)
            #pragma unroll
            for (int j = 0; j < 4; j++)
                #pragma unroll
                for (int q = 0; q < 4; q++) acc[i][j][q] = 0.f;
        {
            const unsigned* A32 = (const unsigned*)As1;
            const unsigned short* Xu = (const unsigned short*)Xs;
            #pragma unroll
            for (int kk16 = 0; kk16 < 128; kk16 += 16){
                unsigned a[2][4], bfr[4][2];
                #pragma unroll
                for (int fm = 0; fm < 2; fm++){
                    int row = wm*32 + fm*16 + (lane >> 2);
                    int c = (kk16 >> 1) + (lane & 3);
                    a[fm][0] = A32[row*68 + c];
                    a[fm][1] = A32[(row+8)*68 + c];
                    a[fm][2] = A32[row*68 + c + 4];
                    a[fm][3] = A32[(row+8)*68 + c + 4];
                }
                #pragma unroll
                for (int fn = 0; fn < 4; fn++){
                    int col = wn*32 + fn*8 + (lane >> 2);
                    int kb = kk16 + (lane & 3)*2;
                    unsigned lo0 = Xu[kb*136 + col],     hi0 = Xu[(kb+1)*136 + col];
                    unsigned lo1 = Xu[(kb+8)*136 + col], hi1 = Xu[(kb+9)*136 + col];
                    bfr[fn][0] = lo0 | (hi0 << 16);
                    bfr[fn][1] = lo1 | (hi1 << 16);
                }
                #pragma unroll
                for (int fm = 0; fm < 2; fm++)
                    #pragma unroll
                    for (int fn = 0; fn < 4; fn++){
                        asm volatile(
                            "mma.sync.aligned.m16n8k16.row.col.f32.bf16.bf16.f32 "
                            "{%0,%1,%2,%3}, {%4,%5,%6,%7}, {%8,%9}, {%0,%1,%2,%3};"
                            : "+f"(acc[fm][fn][0]), "+f"(acc[fm][fn][1]),
                              "+f"(acc[fm][fn][2]), "+f"(acc[fm][fn][3])
                            : "r"(a[fm][0]), "r"(a[fm][1]), "r"(a[fm][2]), "r"(a[fm][3]),
                              "r"(bfr[fn][0]), "r"(bfr[fn][1]));
                    }
            }
        }
        {
            int r = lane >> 2, c2 = (lane & 3)*2;
            #pragma unroll
            for (int fm = 0; fm < 2; fm++){
                int m = wm*32 + fm*16 + r;
                float bb0 = b1v[mc*64 + m], bb1 = b1v[mc*64 + m + 8];
                #pragma unroll
                for (int fn = 0; fn < 4; fn++){
                    int pl = wn*32 + fn*8 + c2;
                    __nv_bfloat162 h2;
                    h2.x = __float2bfloat16(fgelu(acc[fm][fn][0] + bb0));
                    h2.y = __float2bfloat16(fgelu(acc[fm][fn][1] + bb0));
                    *(__nv_bfloat162*)&Hs[m*136 + pl] = h2;
                    __nv_bfloat162 h3;
                    h3.x = __float2bfloat16(fgelu(acc[fm][fn][2] + bb1));
                    h3.y = __float2bfloat16(fgelu(acc[fm][fn][3] + bb1));
                    *(__nv_bfloat162*)&Hs[(m+8)*136 + pl] = h3;
                }
            }
        }
        __syncthreads();
        #pragma unroll
        for (int r = 0; r < 4; r++){
            int i = tid + r*256;
            int row = i >> 3, sg2 = i & 7;
            *(uint4*)&As2[row*72 + sg2*8] =
                *(const uint4*)(g_w2bf + (size_t)row*HID4 + mc*64 + sg2*8);
        }
        __syncthreads();
        {
            const unsigned* A32 = (const unsigned*)As2;
            const unsigned short* Hu = (const unsigned short*)Hs;
            #pragma unroll
            for (int kk16 = 0; kk16 < 64; kk16 += 16){
                unsigned a2[4][4], bfr[4][2];
                #pragma unroll
                for (int fm = 0; fm < 4; fm++){
                    int row = wm*64 + fm*16 + (lane >> 2);
                    int c = (kk16 >> 1) + (lane & 3);
                    a2[fm][0] = A32[row*36 + c];
                    a2[fm][1] = A32[(row+8)*36 + c];
                    a2[fm][2] = A32[row*36 + c + 4];
                    a2[fm][3] = A32[(row+8)*36 + c + 4];
                }
                #pragma unroll
                for (int fn = 0; fn < 4; fn++){
                    int col = wn*32 + fn*8 + (lane >> 2);
                    int kb = kk16 + (lane & 3)*2;
                    unsigned lo0 = Hu[kb*136 + col],     hi0 = Hu[(kb+1)*136 + col];
                    unsigned lo1 = Hu[(kb+8)*136 + col], hi1 = Hu[(kb+9)*136 + col];
                    bfr[fn][0] = lo0 | (hi0 << 16);
                    bfr[fn][1] = lo1 | (hi1 << 16);
                }
                #pragma unroll
                for (int fm = 0; fm < 4; fm++)
                    #pragma unroll
                    for (int fn = 0; fn < 4; fn++){
                        asm volatile(
                            "mma.sync.aligned.m16n8k16.row.col.f32.bf16.bf16.f32 "
                            "{%0,%1,%2,%3}, {%4,%5,%6,%7}, {%8,%9}, {%0,%1,%2,%3};"
                            : "+f"(oacc[fm][fn][0]), "+f"(oacc[fm][fn][1]),
                              "+f"(oacc[fm][fn][2]), "+f"(oacc[fm][fn][3])
                            : "r"(a2[fm][0]), "r"(a2[fm][1]), "r"(a2[fm][2]), "r"(a2[fm][3]),
                              "r"(bfr[fn][0]), "r"(bfr[fn][1]));
                    }
            }
        }
    }

    int r = lane >> 2, c2 = (lane & 3)*2;
    #pragma unroll
    for (int fm = 0; fm < 4; fm++){
        int m = wm*64 + fm*16 + r;
        float bb0 = b2v[m], bb1 = b2v[m+8];
        float g20 = gamma2[m], g21 = gamma2[m+8];
        float sg0 = gamma1[m]*g_sse[bz*DIMC + m];
        float sg1 = gamma1[m+8]*g_sse[bz*DIMC + m + 8];
        #pragma unroll
        for (int fn = 0; fn < 4; fn++){
            int p = p0 + wn*32 + fn*8 + c2;
            if (p < LLC){
                size_t o0 = ((size_t)bz*DIMC + m)*LLC + p;
                size_t o1 = ((size_t)bz*DIMC + m + 8)*LLC + p;
                float2 xv0 = *(const float2*)&x[o0];
                float2 xv1 = *(const float2*)&x[o1];
                __nv_bfloat162 yv0 = *(const __nv_bfloat162*)&g_ybf[o0];
                __nv_bfloat162 yv1 = *(const __nv_bfloat162*)&g_ybf[o1];
                float xr00 = fmaf(sg0, __bfloat162float(yv0.x), xv0.x);
                float xr01 = fmaf(sg0, __bfloat162float(yv0.y), xv0.y);
                float xr10 = fmaf(sg1, __bfloat162float(yv1.x), xv1.x);
                float xr11 = fmaf(sg1, __bfloat162float(yv1.y), xv1.y);
                float2 ov0, ov1;
                ov0.x = fmaf(g20, oacc[fm][fn][0] + bb0, xr00);
                ov0.y = fmaf(g20, oacc[fm][fn][1] + bb0, xr01);
                ov1.x = fmaf(g21, oacc[fm][fn][2] + bb1, xr10);
                ov1.y = fmaf(g21, oacc[fm][fn][3] + bb1, xr11);
                *(float2*)&outf[o0] = ov0;
                *(float2*)&outf[o1] = ov1;
            }
        }
    }
}

// ---------------- launch ----------------
extern "C" void kernel_launch(void* const* d_in, const int* in_sizes, int n_in,
                              void* d_out, int out_size)
{
    const float* x      = (const float*)d_in[0];
    const float* wq     = (const float*)d_in[1];
    const float* wk     = (const float*)d_in[2];
    const float* wv     = (const float*)d_in[3];
    const float* wproj  = (const float*)d_in[4];
    const float* bproj  = (const float*)d_in[5];
    const float* gq     = (const float*)d_in[6];
    const float* gk     = (const float*)d_in[7];
    const float* gv     = (const float*)d_in[8];
    const float* gvm    = (const float*)d_in[9];
    const float* gmlp   = (const float*)d_in[10];
    const float* m_in_w = (const float*)d_in[11];
    const float* m_cw   = (const float*)d_in[12];
    const float* m_cb   = (const float*)d_in[13];
    const float* m_xp   = (const float*)d_in[14];
    const float* m_dtw  = (const float*)d_in[15];
    const float* m_dtb  = (const float*)d_in[16];
    const float* m_Alog = (const float*)d_in[17];
    const float* m_D    = (const float*)d_in[18];
    const float* m_outw = (const float*)d_in[19];
    const float* se_w1  = (const float*)d_in[20];
    const float* se_b1  = (const float*)d_in[21];
    const float* se_w2  = (const float*)d_in[22];
    const float* se_b2  = (const float*)d_in[23];
    const float* mlp_w1 = (const float*)d_in[24];
    const float* mlp_b1 = (const float*)d_in[25];
    const float* mlp_w2 = (const float*)d_in[26];
    const float* mlp_b2 = (const float*)d_in[27];
    const float* gamma1 = (const float*)d_in[28];
    const float* gamma2 = (const float*)d_in[29];
    float* out = (float*)d_out;

    void *p_wqkvbf, *p_wprojbf, *p_winbf, *p_wxbf, *p_woutbf;
    void *p_xn1bf, *p_xn64bf, *p_attnobf, *p_xmbf, *p_ymgbf;
    void *p_qkvbf, *p_tmpbf, *p_pjbf, *p_ybf;
    cudaGetSymbolAddress(&p_wqkvbf, g_wqkvbf);
    cudaGetSymbolAddress(&p_wprojbf, g_wprojbf);
    cudaGetSymbolAddress(&p_winbf, g_winbf);
    cudaGetSymbolAddress(&p_wxbf, g_wxbf);
    cudaGetSymbolAddress(&p_woutbf, g_woutbf);
    cudaGetSymbolAddress(&p_xn1bf, g_xn1bf);
    cudaGetSymbolAddress(&p_xn64bf, g_xn64bf);
    cudaGetSymbolAddress(&p_attnobf, g_attnobf);
    cudaGetSymbolAddress(&p_xmbf, g_xmbf);
    cudaGetSymbolAddress(&p_ymgbf, g_ymgbf);
    cudaGetSymbolAddress(&p_qkvbf, g_qkvbf);
    cudaGetSymbolAddress(&p_tmpbf, g_tmpbf);
    cudaGetSymbolAddress(&p_pjbf, g_pjbf);
    cudaGetSymbolAddress(&p_ybf, g_ybf);

    int mlpf_smem = (128*136 + 64*136 + 64*136 + 128*72)*2;
    cudaFuncSetAttribute(mma_mlpfused_kernel,
        cudaFuncAttributeMaxDynamicSharedMemorySize, mlpf_smem);
    int scan_smem = (256 + 2080*3 + 2560 + 64*128)*4;
    cudaFuncSetAttribute(scan_kernel,
        cudaFuncAttributeMaxDynamicSharedMemorySize, scan_smem);

    cudaStream_t s1;
    cudaStreamCreateWithFlags(&s1, cudaStreamNonBlocking);
    cudaEvent_t evF, evJ;
    cudaEventCreateWithFlags(&evF, cudaEventDisableTiming);
    cudaEventCreateWithFlags(&evJ, cudaEventDisableTiming);

    wprep_kernel<<<256, 256>>>(mlp_w1, mlp_w2, m_xp, wq, wk, wv, gq, gk, gv,
                               wproj, m_in_w, m_outw);
    rms1_kernel<<<784, 256>>>(x, gvm);

    cudaEventRecord(evF, 0);
    cudaStreamWaitEvent(s1, evF, 0);

    // attention branch on s1
    mma_gemm_kernel<64><<<dim3(25, 3, 16), 256, 0, s1>>>(
        (const __nv_bfloat16*)p_wqkvbf, (const __nv_bfloat16*)p_xn1bf,
        (__nv_bfloat16*)p_qkvbf, nullptr, 192, 192, 0);
    attncore_kernel<<<1024, 256, 0, s1>>>();
    mma_gemm_kernel<64><<<dim3(25, 1, 16), 256, 0, s1>>>(
        (const __nv_bfloat16*)p_wprojbf, (const __nv_bfloat16*)p_attnobf,
        (__nv_bfloat16*)p_ybf, bproj, 64, 128, 0);
    cudaEventRecord(evJ, s1);

    // mamba branch on default stream
    mma_gemm_kernel<64><<<dim3(25, 2, 16), 256>>>(
        (const __nv_bfloat16*)p_winbf, (const __nv_bfloat16*)p_xn64bf,
        (__nv_bfloat16*)p_tmpbf, nullptr, 128, 128, 0);
    dwconvT_kernel<<<2048, 256>>>(m_cw, m_cb);
    mma_gemm_kernel<128><<<dim3(25, 3, 16), 256>>>(
        (const __nv_bfloat16*)p_wxbf, (const __nv_bfloat16*)p_xmbf,
        (__nv_bfloat16*)p_pjbf, nullptr, 144, 144, 0);
    transposePJ_kernel<<<1152, 256>>>();
    scan_kernel<<<256, 128, scan_smem>>>(m_dtw, m_dtb, m_Alog, m_D);
    mergegelu_kernel<<<dim3(128, 16), 256>>>();
    mma_gemm_kernel<128><<<dim3(25, 1, 16), 256>>>(
        (const __nv_bfloat16*)p_woutbf, (const __nv_bfloat16*)p_ymgbf,
        (__nv_bfloat16*)p_ybf, nullptr, 64, 128, 64);

    // join attention branch before pool
    cudaStreamWaitEvent(0, evJ, 0);

    pool_kernel<<<BBATCH*DIMC, 256>>>();
    se_kernel<<<BBATCH, 128>>>(se_w1, se_b1, se_w2, se_b2);
    residrms_kernel<<<784, 256>>>(x, gamma1, gmlp);

    mma_mlpfused_kernel<<<dim3(25, 16), 256, mlpf_smem>>>(mlp_b1, mlp_b2, gamma1, gamma2, x, out);
}

// round 15
// speedup vs baseline: 1.0219x; 1.0219x over previous
#include <cuda_runtime.h>
#include <cuda_bf16.h>
#include <math.h>

// ---------------- constants ----------------
#define BBATCH 16
#define DIMC  128
#define HDC   64
#define LLC   3136      // 56*56
#define NTOK  49
#define DI_   128
#define DST_  16
#define KDIR  4
#define CX    36
#define HID4  512

// ---------------- scratch ----------------
__device__ float g_pool[BBATCH*DIMC];
__device__ float g_sse [BBATCH*DIMC];
// bf16 activations / intermediates
__device__ __nv_bfloat16 g_xn1bf [(size_t)BBATCH*HDC*LLC];
__device__ __nv_bfloat16 g_xn64bf[(size_t)BBATCH*HDC*LLC];
__device__ __nv_bfloat16 g_qkvbf [(size_t)BBATCH*192*LLC];
__device__ __nv_bfloat16 g_attnobf[(size_t)BBATCH*HDC*LLC];
__device__ __nv_bfloat16 g_tmpbf [(size_t)BBATCH*DI_*LLC];
__device__ __nv_bfloat16 g_xmbf  [(size_t)BBATCH*DI_*LLC];
__device__ __nv_bfloat16 g_xmTbf [(size_t)BBATCH*DI_*LLC];
__device__ __nv_bfloat16 g_pjbf  [(size_t)BBATCH*KDIR*CX*LLC];
__device__ __nv_bfloat16 g_pjTbf [(size_t)BBATCH*2*CX*LLC];
__device__ __nv_bfloat16 g_ysbf  [(size_t)BBATCH*KDIR*DI_*LLC];
__device__ __nv_bfloat16 g_ymgbf [(size_t)BBATCH*DI_*LLC];
__device__ __nv_bfloat16 g_ybf   [(size_t)BBATCH*DIMC*LLC];
__device__ __nv_bfloat16 g_xnbf  [(size_t)BBATCH*DIMC*LLC];
// bf16 weights
__device__ __nv_bfloat16 g_w1bf[HID4*DIMC];
__device__ __nv_bfloat16 g_w2bf[DIMC*HID4];
__device__ __nv_bfloat16 g_wqkvbf[192*HDC];
__device__ __nv_bfloat16 g_wprojbf[HDC*HDC];
__device__ __nv_bfloat16 g_winbf[DI_*HDC];
__device__ __nv_bfloat16 g_wxbf[192*DI_];     // 144 real rows, zero-padded
__device__ __nv_bfloat16 g_woutbf[HDC*DI_];

// ---------------- helpers ----------------
__device__ __forceinline__ float fgelu(float x){
    float u = 0.7978845608028654f*(x + 0.044715f*x*x*x);
    float t;
    asm("tanh.approx.f32 %0, %1;" : "=f"(t) : "f"(u));
    return 0.5f*x*(1.f+t);
}
__device__ __forceinline__ float fsilu(float x){
    return x * (1.f/(1.f+__expf(-x)));
}

// ---------------- 0. weight prep ----------------
__global__ void wprep_kernel(const float* __restrict__ w1, const float* __restrict__ w2,
    const float* __restrict__ xp,
    const float* __restrict__ wq, const float* __restrict__ wk, const float* __restrict__ wv,
    const float* __restrict__ gq, const float* __restrict__ gk, const float* __restrict__ gv,
    const float* __restrict__ wproj, const float* __restrict__ m_in_w,
    const float* __restrict__ m_outw)
{
    int i = blockIdx.x*256 + threadIdx.x;
    if (i < HID4*DIMC) g_w1bf[i] = __float2bfloat16(w1[i]);
    if (i < DIMC*HID4) g_w2bf[i] = __float2bfloat16(w2[i]);
    if (i < 192*DI_){
        if (i < KDIR*CX*DI_){
            int o = i >> 7, d = i & 127;
            int k = o / CX, c = o - k*CX;
            g_wxbf[i] = __float2bfloat16(xp[(k*DI_ + d)*CX + c]);
        } else {
            g_wxbf[i] = __float2bfloat16(0.f);
        }
    }
    if (i < 192*HDC){
        int o = i >> 6, c = i & 63;
        float v;
        if (o < 64)       v = wq[o*64 + c]*gq[c];
        else if (o < 128) v = wk[(o-64)*64 + c]*gk[c];
        else              v = wv[(o-128)*64 + c]*gv[c];
        g_wqkvbf[i] = __float2bfloat16(v);
    }
    if (i < HDC*HDC)  g_wprojbf[i] = __float2bfloat16(wproj[i]);
    if (i < DI_*HDC)  g_winbf[i]   = __float2bfloat16(m_in_w[i]);
    if (i < HDC*DI_)  g_woutbf[i]  = __float2bfloat16(m_outw[i]);
}

// ---------------- 1. fused rms for both halves -> bf16 ----------------
__global__ void rms1_kernel(const float* __restrict__ x, const float* __restrict__ gvm)
{
    __shared__ float ssum[256];
    int tid = threadIdx.x;
    int g = tid >> 6, px = tid & 63;
    int gp = blockIdx.x*64 + px;
    int b = gp / LLC, p = gp - b*LLC;
    const float* xb = x + ((size_t)b*DIMC + g*32)*LLC + p;
    float v[32];
    float s = 0.f;
    #pragma unroll
    for (int i = 0; i < 32; i++){ v[i] = xb[(size_t)i*LLC]; s += v[i]*v[i]; }
    ssum[tid] = s;
    __syncthreads();
    float tot = (g < 2) ? (ssum[px] + ssum[64+px]) : (ssum[128+px] + ssum[192+px]);
    float inv = rsqrtf(tot*(1.f/64.f) + 1e-5f);
    if (g < 2){
        __nv_bfloat16* ob = g_xn1bf + ((size_t)b*HDC + g*32)*LLC + p;
        #pragma unroll
        for (int i = 0; i < 32; i++) ob[(size_t)i*LLC] = __float2bfloat16(v[i]*inv);
    } else {
        int c0 = (g-2)*32;
        __nv_bfloat16* ob = g_xn64bf + ((size_t)b*HDC + c0)*LLC + p;
        #pragma unroll
        for (int i = 0; i < 32; i++) ob[(size_t)i*LLC] = __float2bfloat16(v[i]*inv*gvm[c0+i]);
    }
}

// ---------------- generic bf16 tensor-core GEMM (bf16 out) ----------------
template<int K>
__global__ __launch_bounds__(256) void mma_gemm_kernel(
    const __nv_bfloat16* __restrict__ W, const __nv_bfloat16* __restrict__ X,
    __nv_bfloat16* __restrict__ OUT, const float* __restrict__ bias,
    int Mtot, int ostride, int o_off)
{
    __shared__ __nv_bfloat16 As[64*40];
    __shared__ __nv_bfloat16 Bs[32*136];
    int tid = threadIdx.x;
    int lane = tid & 31, wid = tid >> 5;
    int wm = wid >> 2, wn = wid & 3;
    int p0 = blockIdx.x*128;
    int m0 = blockIdx.y*64;
    int bz = blockIdx.z;

    float acc[2][4][4];
    #pragma unroll
    for (int i = 0; i < 2; i++)
        #pragma unroll
        for (int j = 0; j < 4; j++)
            #pragma unroll
            for (int q = 0; q < 4; q++) acc[i][j][q] = 0.f;

    for (int kc = 0; kc < K; kc += 32){
        __syncthreads();
        {
            int row = tid >> 2, seg = tid & 3;
            uint4 v = *(const uint4*)(W + (size_t)(m0 + row)*K + kc + seg*8);
            *(uint4*)(&As[row*40 + seg*8]) = v;
        }
        {
            int kk = tid >> 3, pg = tid & 7;
            const __nv_bfloat16* src = X + ((size_t)bz*K + kc + kk)*LLC + p0 + pg*16;
            #pragma unroll
            for (int r = 0; r < 2; r++){
                int p = p0 + pg*16 + r*8;
                uint4 v = make_uint4(0u,0u,0u,0u);
                if (p < LLC) v = *(const uint4*)(src + r*8);
                *(uint4*)(&Bs[kk*136 + pg*16 + r*8]) = v;
            }
        }
        __syncthreads();
        #pragma unroll
        for (int ks = 0; ks < 2; ks++){
            int kk16 = ks*16;
            unsigned a[2][4], bfr[4][2];
            const unsigned* As32 = (const unsigned*)As;
            #pragma unroll
            for (int fm = 0; fm < 2; fm++){
                int row = wm*32 + fm*16 + (lane >> 2);
                int c = (kk16 >> 1) + (lane & 3);
                a[fm][0] = As32[row*20 + c];
                a[fm][1] = As32[(row+8)*20 + c];
                a[fm][2] = As32[row*20 + c + 4];
                a[fm][3] = As32[(row+8)*20 + c + 4];
            }
            const unsigned short* Bu = (const unsigned short*)Bs;
            #pragma unroll
            for (int fn = 0; fn < 4; fn++){
                int col = wn*32 + fn*8 + (lane >> 2);
                int kb = kk16 + (lane & 3)*2;
                unsigned lo0 = Bu[kb*136 + col],     hi0 = Bu[(kb+1)*136 + col];
                unsigned lo1 = Bu[(kb+8)*136 + col], hi1 = Bu[(kb+9)*136 + col];
                bfr[fn][0] = lo0 | (hi0 << 16);
                bfr[fn][1] = lo1 | (hi1 << 16);
            }
            #pragma unroll
            for (int fm = 0; fm < 2; fm++)
                #pragma unroll
                for (int fn = 0; fn < 4; fn++){
                    asm volatile(
                        "mma.sync.aligned.m16n8k16.row.col.f32.bf16.bf16.f32 "
                        "{%0,%1,%2,%3}, {%4,%5,%6,%7}, {%8,%9}, {%0,%1,%2,%3};"
                        : "+f"(acc[fm][fn][0]), "+f"(acc[fm][fn][1]),
                          "+f"(acc[fm][fn][2]), "+f"(acc[fm][fn][3])
                        : "r"(a[fm][0]), "r"(a[fm][1]), "r"(a[fm][2]), "r"(a[fm][3]),
                          "r"(bfr[fn][0]), "r"(bfr[fn][1]));
                }
        }
    }

    int r = lane >> 2, c2 = (lane & 3)*2;
    #pragma unroll
    for (int fm = 0; fm < 2; fm++){
        int m = m0 + wm*32 + fm*16 + r;
        #pragma unroll
        for (int fn = 0; fn < 4; fn++){
            int p = p0 + wn*32 + fn*8 + c2;
            if (p < LLC){
                #pragma unroll
                for (int half = 0; half < 2; half++){
                    int mm = m + half*8;
                    if (mm < Mtot){
                        float bv = bias ? bias[mm] : 0.f;
                        float v0 = acc[fm][fn][half*2+0] + bv;
                        float v1 = acc[fm][fn][half*2+1] + bv;
                        size_t off = ((size_t)bz*ostride + o_off + mm)*LLC + p;
                        __nv_bfloat162 h2;
                        h2.x = __float2bfloat16(v0);
                        h2.y = __float2bfloat16(v1);
                        *(__nv_bfloat162*)&OUT[off] = h2;
                    }
                }
            }
        }
    }
}

// ---------------- 2. window-attention core: bf16x2 math, single-pass softmax ----------------
__global__ __launch_bounds__(256, 3) void attncore_kernel(void)
{
    __shared__ __nv_bfloat16 q_s[8*49*8];
    __shared__ __nv_bfloat16 k_s[8*49*8];
    __shared__ __nv_bfloat16 v_s[8*49*8];
    int tid = threadIdx.x, lane = tid & 31, h = tid >> 5;
    int bw = blockIdx.x;
    int b = bw >> 6, wh = (bw >> 3) & 7, wwi = bw & 7;
    int pbase = (wh*7)*56 + wwi*7;
    const __nv_bfloat16* qb = g_qkvbf + ((size_t)b*192 + h*8)*LLC;

    for (int it = lane; it < 392; it += 32){
        int dd = it / 49, j = it - dd*49;
        int pix = pbase + (j/7)*56 + (j - (j/7)*7);
        size_t base = (size_t)dd*LLC + pix;
        float qv = __bfloat162float(qb[base]) * 0.35355339059327373f;
        q_s[(h*49+j)*8+dd] = __float2bfloat16(qv);
        k_s[(h*49+j)*8+dd] = qb[64*LLC + base];
        v_s[(h*49+j)*8+dd] = qb[128*LLC + base];
    }
    __syncwarp();

    __nv_bfloat16* ob = g_attnobf + (size_t)b*HDC*LLC;
    #pragma unroll
    for (int rr = 0; rr < 2; rr++){
        int r = lane + rr*32;
        if (r < 49){
            uint4 qr = *(const uint4*)&q_s[(h*49+r)*8];
            const __nv_bfloat162* q2 = (const __nv_bfloat162*)&qr;
            float sum = 0.f;
            __nv_bfloat162 o2[4];
            __nv_bfloat162 zz = __float2bfloat162_rn(0.f);
            o2[0] = zz; o2[1] = zz; o2[2] = zz; o2[3] = zz;
            #pragma unroll 7
            for (int j = 0; j < 49; j++){
                uint4 kr = *(const uint4*)&k_s[(h*49+j)*8];
                const __nv_bfloat162* k2 = (const __nv_bfloat162*)&kr;
                __nv_bfloat162 a2 = __hmul2(q2[0], k2[0]);
                a2 = __hfma2(q2[1], k2[1], a2);
                a2 = __hfma2(q2[2], k2[2], a2);
                a2 = __hfma2(q2[3], k2[3], a2);
                float s = __bfloat162float(a2.x) + __bfloat162float(a2.y);
                float e = __expf(s);
                sum += e;
                __nv_bfloat162 e2 = __float2bfloat162_rn(e);
                uint4 vr = *(const uint4*)&v_s[(h*49+j)*8];
                const __nv_bfloat162* v2 = (const __nv_bfloat162*)&vr;
                o2[0] = __hfma2(e2, v2[0], o2[0]);
                o2[1] = __hfma2(e2, v2[1], o2[1]);
                o2[2] = __hfma2(e2, v2[2], o2[2]);
                o2[3] = __hfma2(e2, v2[3], o2[3]);
            }
            float rinv = 1.f/sum;
            int pr = pbase + (r/7)*56 + (r - (r/7)*7);
            #pragma unroll
            for (int g2i = 0; g2i < 4; g2i++){
                ob[(size_t)(h*8+g2i*2+0)*LLC + pr] =
                    __float2bfloat16(__bfloat162float(o2[g2i].x)*rinv);
                ob[(size_t)(h*8+g2i*2+1)*LLC + pr] =
                    __float2bfloat16(__bfloat162float(o2[g2i].y)*rinv);
            }
        }
    }
}

// ---------------- 3. fused depthwise 3x3 + silu -> bf16 (natural + transposed) ----------------
__global__ __launch_bounds__(256) void dwconvT_kernel(const float* __restrict__ cw,
                                                      const float* __restrict__ cb)
{
    __shared__ float in_s[58*58];
    __shared__ float out_s[56*57 + 8];
    int tid = threadIdx.x;
    int bc = blockIdx.x;
    int c = bc & (DI_-1);
    const __nv_bfloat16* src = g_tmpbf + (size_t)bc*LLC;
    float wc[9];
    #pragma unroll
    for (int i = 0; i < 9; i++) wc[i] = cw[c*9 + i];
    float bcv = cb[c];

    for (int i = tid; i < 58*58; i += 256){
        int row = i / 58, col = i - row*58;
        int hy = row - 1, wx = col - 1;
        float v = 0.f;
        if (hy >= 0 && hy < 56 && wx >= 0 && wx < 56) v = __bfloat162float(src[hy*56 + wx]);
        in_s[i] = v;
    }
    __syncthreads();
    __nv_bfloat16* db = g_xmbf + (size_t)bc*LLC;
    for (int p = tid; p < LLC; p += 256){
        int h = p / 56, w = p - h*56;
        const float* ip = &in_s[h*58 + w];
        float acc = bcv;
        acc = fmaf(ip[0],     wc[0], acc);
        acc = fmaf(ip[1],     wc[1], acc);
        acc = fmaf(ip[2],     wc[2], acc);
        acc = fmaf(ip[58],    wc[3], acc);
        acc = fmaf(ip[59],    wc[4], acc);
        acc = fmaf(ip[60],    wc[5], acc);
        acc = fmaf(ip[116],   wc[6], acc);
        acc = fmaf(ip[117],   wc[7], acc);
        acc = fmaf(ip[118],   wc[8], acc);
        float val = fsilu(acc);
        db[p] = __float2bfloat16(val);
        out_s[h*57 + w] = val;
    }
    __syncthreads();
    __nv_bfloat16* dt = g_xmTbf + (size_t)bc*LLC;
    for (int i = tid; i < LLC; i += 256){
        int hh = i / 56, ww = i - hh*56;
        dt[i] = __float2bfloat16(out_s[ww*57 + hh]);
    }
}

// ---------------- 4. transpose pj(k1,k3) slices (bf16) ----------------
__global__ void transposePJ_kernel(void)
{
    __shared__ float sm[56*57 + 8];
    int j = blockIdx.x;
    int b = j / (2*CX), r = j - b*(2*CX);
    int kk = (r < CX) ? 1 : 3;
    int c = (r < CX) ? r : r - CX;
    const __nv_bfloat16* src = g_pjbf + ((size_t)b*KDIR*CX + kk*CX + c)*LLC;
    __nv_bfloat16* dst = g_pjTbf + (size_t)j*LLC;
    int tid = threadIdx.x;
    for (int i = tid; i < LLC; i += 256){
        int hh = i/56, ww = i - hh*56;
        sm[hh*57 + ww] = __bfloat162float(src[i]);
    }
    __syncthreads();
    for (int i = tid; i < LLC; i += 256){
        int hh = i/56, ww = i - hh*56;
        dst[i] = __float2bfloat16(sm[ww*57 + hh]);
    }
}

// ---------------- 5. selective scan (R12 form: shfl reduce, static smem) ----------------
__global__ __launch_bounds__(128) void scan_kernel(const float* __restrict__ dtw,
    const float* __restrict__ dtb, const float* __restrict__ alog, const float* __restrict__ Dp)
{
    __shared__ float dts [4*64];
    __shared__ float Uc  [32*65];
    __shared__ float du_s[32*65];
    __shared__ float p1_s[32*65];
    __shared__ float Pt  [64*40];
    __shared__ float Yc  [32*65];
    __shared__ float dtw4s[32][4];
    __shared__ float dtbs[32];

    int tid = threadIdx.x;
    int blk = blockIdx.x;
    int q = blk & 3;
    int k = (blk >> 2) & 3;
    int b = blk >> 4;
    int ch = tid >> 2;
    int sub = tid & 3;
    int ng = sub*4;
    int d = q*32 + ch;
    int kd = k*DI_ + d;

    if (tid < 32){
        int kdl = k*DI_ + q*32 + tid;
        dtbs[tid] = dtb[kdl];
        #pragma unroll
        for (int r = 0; r < 4; r++) dtw4s[tid][r] = dtw[kdl*4 + r];
    }
    float A2[4];
    bool structured = true;
    #pragma unroll
    for (int n = 0; n < 4; n++){
        A2[n] = -__expf(alog[kd*DST_ + ng + n]);
        if (fabsf(A2[n] + (float)(ng + n + 1)) > 1e-3f) structured = false;
    }
    float hst[4] = {0.f, 0.f, 0.f, 0.f};
    float Dd_own = Dp[kd];

    bool fwd = (k < 2);
    const __nv_bfloat16* usrc = ((k == 0) || (k == 2))
        ? (g_xmbf  + ((size_t)b*DI_ + q*32)*LLC)
        : (g_xmTbf + ((size_t)b*DI_ + q*32)*LLC);
    const __nv_bfloat16* psrc;
    if (k == 0)      psrc = g_pjbf + ((size_t)b*KDIR*CX + 0*CX)*LLC;
    else if (k == 2) psrc = g_pjbf + ((size_t)b*KDIR*CX + 2*CX)*LLC;
    else if (k == 1) psrc = g_pjTbf + ((size_t)b*2*CX)*LLC;
    else             psrc = g_pjTbf + ((size_t)b*2*CX + CX)*LLC;
    __nv_bfloat16* yb = g_ysbf + (((size_t)(b*KDIR + k))*DI_ + q*32)*LLC;
    __syncthreads();

    for (int s0 = 0; s0 < LLC; s0 += 64){
        #pragma unroll
        for (int rr = 0; rr < 16; rr++){
            int i = tid + rr*128;
            int cc = i >> 6, t = i & 63;
            int s = s0 + t;
            int gi = fwd ? s : (LLC-1-s);
            Uc[cc*65 + t] = __bfloat162float(usrc[(size_t)cc*LLC + gi]);
        }
        {
            int i = tid, i2 = tid + 128;
            int r = i >> 6, t = i & 63;
            int s = s0 + t;
            dts[i] = __bfloat162float(psrc[(size_t)r*LLC + (fwd ? s : (LLC-1-s))]);
            r = i2 >> 6; t = i2 & 63; s = s0 + t;
            dts[i2] = __bfloat162float(psrc[(size_t)r*LLC + (fwd ? s : (LLC-1-s))]);
        }
        #pragma unroll
        for (int rr = 0; rr < 16; rr++){
            int i = tid + rr*128;
            int cc = i >> 6, t = i & 63;
            int s = s0 + t;
            Pt[t*40 + cc] = __bfloat162float(psrc[(size_t)(4+cc)*LLC + (fwd ? s : (LLC-1-s))]);
        }
        __syncthreads();
        #pragma unroll
        for (int rr = 0; rr < 16; rr++){
            int i = tid + rr*128;
            int cc = i >> 6, t = i & 63;
            float dtr = dtbs[cc];
            dtr = fmaf(dts[t],       dtw4s[cc][0], dtr);
            dtr = fmaf(dts[64 + t],  dtw4s[cc][1], dtr);
            dtr = fmaf(dts[128 + t], dtw4s[cc][2], dtr);
            dtr = fmaf(dts[192 + t], dtw4s[cc][3], dtr);
            float e = __expf(dtr);
            float delta = (dtr > 20.f) ? dtr : __logf(1.f + e);
            du_s[cc*65 + t] = delta * Uc[cc*65 + t];
            p1_s[cc*65 + t] = __expf(-delta);
        }
        __syncthreads();
        for (int t = 0; t < 64; t++){
            float du = du_s[ch*65 + t];
            float p1 = p1_s[ch*65 + t];
            float4 Bv = *(const float4*)&Pt[t*40 + ng];
            float4 Cv = *(const float4*)&Pt[t*40 + 16 + ng];
            float pe0, pe1, pe2, pe3;
            if (structured){
                float p2 = p1*p1;
                float p4 = p2*p2;
                float p8 = p4*p4;
                float base = p1;
                if (sub & 1) base *= p4;
                if (sub & 2) base *= p8;
                pe0 = base;
                pe1 = base*p1;
                pe2 = base*p2;
                pe3 = pe2*p1;
            } else {
                pe0 = __powf(p1, -A2[0]);
                pe1 = __powf(p1, -A2[1]);
                pe2 = __powf(p1, -A2[2]);
                pe3 = __powf(p1, -A2[3]);
            }
            hst[0] = fmaf(pe0, hst[0], du*Bv.x);
            hst[1] = fmaf(pe1, hst[1], du*Bv.y);
            hst[2] = fmaf(pe2, hst[2], du*Bv.z);
            hst[3] = fmaf(pe3, hst[3], du*Bv.w);
            float y = hst[0]*Cv.x;
            y = fmaf(hst[1], Cv.y, y);
            y = fmaf(hst[2], Cv.z, y);
            y = fmaf(hst[3], Cv.w, y);
            y += __shfl_xor_sync(0xffffffffu, y, 1);
            y += __shfl_xor_sync(0xffffffffu, y, 2);
            if (sub == 0){
                float u = Uc[ch*65 + t];
                Yc[ch*65 + t] = fmaf(u, Dd_own, y);
            }
        }
        __syncthreads();
        #pragma unroll
        for (int rr = 0; rr < 16; rr++){
            int i = tid + rr*128;
            int cc = i >> 6, t = i & 63;
            yb[(size_t)cc*LLC + s0 + t] = __float2bfloat16(Yc[cc*65 + t]);
        }
        __syncthreads();
    }
}

// ---------------- 6. cross_merge + gelu -> bf16 ----------------
__global__ void mergegelu_kernel(void)
{
    __shared__ float sm1[56*57 + 8];
    __shared__ float sm3[56*57 + 8];
    int tid = threadIdx.x;
    int dch = blockIdx.x;
    int b   = blockIdx.y;
    const __nv_bfloat16* y0p = g_ysbf + (((size_t)(b*KDIR + 0))*DI_ + dch)*LLC;
    const __nv_bfloat16* y1p = g_ysbf + (((size_t)(b*KDIR + 1))*DI_ + dch)*LLC;
    const __nv_bfloat16* y2p = g_ysbf + (((size_t)(b*KDIR + 2))*DI_ + dch)*LLC;
    const __nv_bfloat16* y3p = g_ysbf + (((size_t)(b*KDIR + 3))*DI_ + dch)*LLC;
    for (int i = tid; i < LLC; i += 256){
        int hh = i / 56, ww = i - hh*56;
        sm1[hh*57 + ww] = __bfloat162float(y1p[i]);
        sm3[hh*57 + ww] = __bfloat162float(y3p[i]);
    }
    __syncthreads();
    __nv_bfloat16* op = g_ymgbf + ((size_t)b*DI_ + dch)*LLC;
    for (int p = tid; p < LLC; p += 256){
        int hh = p / 56, ww = p - hh*56;
        float v = __bfloat162float(y0p[p]) + __bfloat162float(y2p[LLC-1-p])
                + sm1[ww*57 + hh] + sm3[(55-ww)*57 + (55-hh)];
        op[p] = __float2bfloat16(fgelu(v));
    }
}

// ---------------- 7. pool / SE ----------------
__global__ void pool_kernel(void)
{
    __shared__ float red[256];
    int bc = blockIdx.x;
    const __nv_bfloat16* yb = g_ybf + (size_t)bc*LLC;
    float s = 0.f;
    for (int i = threadIdx.x; i < LLC; i += 256) s += __bfloat162float(yb[i]);
    red[threadIdx.x] = s;
    __syncthreads();
    for (int st = 128; st > 0; st >>= 1){
        if (threadIdx.x < st) red[threadIdx.x] += red[threadIdx.x + st];
        __syncthreads();
    }
    if (threadIdx.x == 0) g_pool[bc] = red[0]*(1.f/LLC);
}

__global__ void se_kernel(const float* __restrict__ w1, const float* __restrict__ b1,
    const float* __restrict__ w2, const float* __restrict__ b2)
{
    __shared__ float pv[DIMC];
    __shared__ float h1[32];
    int tid = threadIdx.x;
    int b = blockIdx.x;
    if (tid < DIMC) pv[tid] = g_pool[b*DIMC + tid];
    __syncthreads();
    if (tid < 32){
        float acc = b1[tid];
        #pragma unroll
        for (int c = 0; c < DIMC; c++) acc = fmaf(pv[c], w1[tid*DIMC + c], acc);
        h1[tid] = fmaxf(acc, 0.f);
    }
    __syncthreads();
    if (tid < DIMC){
        float acc = b2[tid];
        #pragma unroll
        for (int j = 0; j < 32; j++) acc = fmaf(h1[j], w2[tid*32 + j], acc);
        g_sse[b*DIMC + tid] = 1.f/(1.f + __expf(-acc));
    }
}

// ---------------- 8. residual1 + rms2d -> bf16 (xn only) ----------------
__global__ void residrms_kernel(const float* __restrict__ x,
    const float* __restrict__ gamma1, const float* __restrict__ gmlp)
{
    __shared__ float ssum[256];
    __shared__ float sg[DIMC];
    int tid = threadIdx.x;
    int g = tid >> 6, px = tid & 63;
    int b = (blockIdx.x*64) / LLC;
    int p = blockIdx.x*64 - b*LLC + px;
    if (tid < DIMC) sg[tid] = gamma1[tid]*g_sse[b*DIMC + tid];
    __syncthreads();
    const float* xb = x + ((size_t)b*DIMC + g*32)*LLC + p;
    const __nv_bfloat16* yb = g_ybf + ((size_t)b*DIMC + g*32)*LLC + p;
    float v[32];
    float s = 0.f;
    #pragma unroll
    for (int i = 0; i < 32; i++){
        float val = fmaf(sg[g*32+i], __bfloat162float(yb[(size_t)i*LLC]), xb[(size_t)i*LLC]);
        v[i] = val;
        s += val*val;
    }
    ssum[tid] = s;
    __syncthreads();
    float tot = ssum[px] + ssum[64+px] + ssum[128+px] + ssum[192+px];
    float inv = rsqrtf(tot*(1.f/DIMC) + 1e-5f);
    __nv_bfloat16* ob = g_xnbf + ((size_t)b*DIMC + g*32)*LLC + p;
    #pragma unroll
    for (int i = 0; i < 32; i++)
        ob[(size_t)i*LLC] = __float2bfloat16(v[i]*inv*gmlp[g*32+i]);
}

// ---------------- 9. fully fused MLP ----------------
__global__ __launch_bounds__(256) void mma_mlpfused_kernel(
    const float* __restrict__ b1v, const float* __restrict__ b2v,
    const float* __restrict__ gamma1, const float* __restrict__ gamma2,
    const float* __restrict__ x, float* __restrict__ outf)
{
    extern __shared__ __nv_bfloat16 smx[];
    __nv_bfloat16* Xs  = smx;
    __nv_bfloat16* Hs  = Xs + 128*136;
    __nv_bfloat16* As1 = Hs + 64*136;
    __nv_bfloat16* As2 = As1 + 64*136;
    int tid = threadIdx.x;
    int lane = tid & 31, wid = tid >> 5;
    int wm = wid >> 2, wn = wid & 3;
    int p0 = blockIdx.x*128;
    int bz = blockIdx.y;

    {
        const __nv_bfloat16* src = g_xnbf + (size_t)bz*DIMC*LLC;
        #pragma unroll
        for (int r = 0; r < 8; r++){
            int i = tid + r*256;
            int row = i >> 4, pg = i & 15;
            int p = p0 + pg*8;
            uint4 v = make_uint4(0u,0u,0u,0u);
            if (p < LLC) v = *(const uint4*)(src + (size_t)row*LLC + p);
            *(uint4*)&Xs[row*136 + pg*8] = v;
        }
    }

    float oacc[4][4][4];
    #pragma unroll
    for (int i = 0; i < 4; i++)
        #pragma unroll
        for (int j = 0; j < 4; j++)
            #pragma unroll
            for (int q = 0; q < 4; q++) oacc[i][j][q] = 0.f;
    __syncthreads();

    for (int mc = 0; mc < 8; mc++){
        #pragma unroll
        for (int r = 0; r < 4; r++){
            int i = tid + r*256;
            int row = i >> 4, pg = i & 15;
            *(uint4*)&As1[row*136 + pg*8] =
                *(const uint4*)(g_w1bf + (size_t)(mc*64 + row)*DIMC + pg*8);
        }
        __syncthreads();

        float acc[2][4][4];
        #pragma unroll
        for (int i = 0; i < 2; i++)
            #pragma unroll
            for (int j = 0; j < 4; j++)
                #pragma unroll
                for (int q = 0; q < 4; q++) acc[i][j][q] = 0.f;
        {
            const unsigned* A32 = (const unsigned*)As1;
            const unsigned short* Xu = (const unsigned short*)Xs;
            #pragma unroll
            for (int kk16 = 0; kk16 < 128; kk16 += 16){
                unsigned a[2][4], bfr[4][2];
                #pragma unroll
                for (int fm = 0; fm < 2; fm++){
                    int row = wm*32 + fm*16 + (lane >> 2);
                    int c = (kk16 >> 1) + (lane & 3);
                    a[fm][0] = A32[row*68 + c];
                    a[fm][1] = A32[(row+8)*68 + c];
                    a[fm][2] = A32[row*68 + c + 4];
                    a[fm][3] = A32[(row+8)*68 + c + 4];
                }
                #pragma unroll
                for (int fn = 0; fn < 4; fn++){
                    int col = wn*32 + fn*8 + (lane >> 2);
                    int kb = kk16 + (lane & 3)*2;
                    unsigned lo0 = Xu[kb*136 + col],     hi0 = Xu[(kb+1)*136 + col];
                    unsigned lo1 = Xu[(kb+8)*136 + col], hi1 = Xu[(kb+9)*136 + col];
                    bfr[fn][0] = lo0 | (hi0 << 16);
                    bfr[fn][1] = lo1 | (hi1 << 16);
                }
                #pragma unroll
                for (int fm = 0; fm < 2; fm++)
                    #pragma unroll
                    for (int fn = 0; fn < 4; fn++){
                        asm volatile(
                            "mma.sync.aligned.m16n8k16.row.col.f32.bf16.bf16.f32 "
                            "{%0,%1,%2,%3}, {%4,%5,%6,%7}, {%8,%9}, {%0,%1,%2,%3};"
                            : "+f"(acc[fm][fn][0]), "+f"(acc[fm][fn][1]),
                              "+f"(acc[fm][fn][2]), "+f"(acc[fm][fn][3])
                            : "r"(a[fm][0]), "r"(a[fm][1]), "r"(a[fm][2]), "r"(a[fm][3]),
                              "r"(bfr[fn][0]), "r"(bfr[fn][1]));
                    }
            }
        }
        {
            int r = lane >> 2, c2 = (lane & 3)*2;
            #pragma unroll
            for (int fm = 0; fm < 2; fm++){
                int m = wm*32 + fm*16 + r;
                float bb0 = b1v[mc*64 + m], bb1 = b1v[mc*64 + m + 8];
                #pragma unroll
                for (int fn = 0; fn < 4; fn++){
                    int pl = wn*32 + fn*8 + c2;
                    __nv_bfloat162 h2;
                    h2.x = __float2bfloat16(fgelu(acc[fm][fn][0] + bb0));
                    h2.y = __float2bfloat16(fgelu(acc[fm][fn][1] + bb0));
                    *(__nv_bfloat162*)&Hs[m*136 + pl] = h2;
                    __nv_bfloat162 h3;
                    h3.x = __float2bfloat16(fgelu(acc[fm][fn][2] + bb1));
                    h3.y = __float2bfloat16(fgelu(acc[fm][fn][3] + bb1));
                    *(__nv_bfloat162*)&Hs[(m+8)*136 + pl] = h3;
                }
            }
        }
        __syncthreads();
        #pragma unroll
        for (int r = 0; r < 4; r++){
            int i = tid + r*256;
            int row = i >> 3, sg2 = i & 7;
            *(uint4*)&As2[row*72 + sg2*8] =
                *(const uint4*)(g_w2bf + (size_t)row*HID4 + mc*64 + sg2*8);
        }
        __syncthreads();
        {
            const unsigned* A32 = (const unsigned*)As2;
            const unsigned short* Hu = (const unsigned short*)Hs;
            #pragma unroll
            for (int kk16 = 0; kk16 < 64; kk16 += 16){
                unsigned a2[4][4], bfr[4][2];
                #pragma unroll
                for (int fm = 0; fm < 4; fm++){
                    int row = wm*64 + fm*16 + (lane >> 2);
                    int c = (kk16 >> 1) + (lane & 3);
                    a2[fm][0] = A32[row*36 + c];
                    a2[fm][1] = A32[(row+8)*36 + c];
                    a2[fm][2] = A32[row*36 + c + 4];
                    a2[fm][3] = A32[(row+8)*36 + c + 4];
                }
                #pragma unroll
                for (int fn = 0; fn < 4; fn++){
                    int col = wn*32 + fn*8 + (lane >> 2);
                    int kb = kk16 + (lane & 3)*2;
                    unsigned lo0 = Hu[kb*136 + col],     hi0 = Hu[(kb+1)*136 + col];
                    unsigned lo1 = Hu[(kb+8)*136 + col], hi1 = Hu[(kb+9)*136 + col];
                    bfr[fn][0] = lo0 | (hi0 << 16);
                    bfr[fn][1] = lo1 | (hi1 << 16);
                }
                #pragma unroll
                for (int fm = 0; fm < 4; fm++)
                    #pragma unroll
                    for (int fn = 0; fn < 4; fn++){
                        asm volatile(
                            "mma.sync.aligned.m16n8k16.row.col.f32.bf16.bf16.f32 "
                            "{%0,%1,%2,%3}, {%4,%5,%6,%7}, {%8,%9}, {%0,%1,%2,%3};"
                            : "+f"(oacc[fm][fn][0]), "+f"(oacc[fm][fn][1]),
                              "+f"(oacc[fm][fn][2]), "+f"(oacc[fm][fn][3])
                            : "r"(a2[fm][0]), "r"(a2[fm][1]), "r"(a2[fm][2]), "r"(a2[fm][3]),
                              "r"(bfr[fn][0]), "r"(bfr[fn][1]));
                    }
            }
        }
    }

    int r = lane >> 2, c2 = (lane & 3)*2;
    #pragma unroll
    for (int fm = 0; fm < 4; fm++){
        int m = wm*64 + fm*16 + r;
        float bb0 = b2v[m], bb1 = b2v[m+8];
        float g20 = gamma2[m], g21 = gamma2[m+8];
        float sg0 = gamma1[m]*g_sse[bz*DIMC + m];
        float sg1 = gamma1[m+8]*g_sse[bz*DIMC + m + 8];
        #pragma unroll
        for (int fn = 0; fn < 4; fn++){
            int p = p0 + wn*32 + fn*8 + c2;
            if (p < LLC){
                size_t o0 = ((size_t)bz*DIMC + m)*LLC + p;
                size_t o1 = ((size_t)bz*DIMC + m + 8)*LLC + p;
                float2 xv0 = *(const float2*)&x[o0];
                float2 xv1 = *(const float2*)&x[o1];
                __nv_bfloat162 yv0 = *(const __nv_bfloat162*)&g_ybf[o0];
                __nv_bfloat162 yv1 = *(const __nv_bfloat162*)&g_ybf[o1];
                float xr00 = fmaf(sg0, __bfloat162float(yv0.x), xv0.x);
                float xr01 = fmaf(sg0, __bfloat162float(yv0.y), xv0.y);
                float xr10 = fmaf(sg1, __bfloat162float(yv1.x), xv1.x);
                float xr11 = fmaf(sg1, __bfloat162float(yv1.y), xv1.y);
                float2 ov0, ov1;
                ov0.x = fmaf(g20, oacc[fm][fn][0] + bb0, xr00);
                ov0.y = fmaf(g20, oacc[fm][fn][1] + bb0, xr01);
                ov1.x = fmaf(g21, oacc[fm][fn][2] + bb1, xr10);
                ov1.y = fmaf(g21, oacc[fm][fn][3] + bb1, xr11);
                *(float2*)&outf[o0] = ov0;
                *(float2*)&outf[o1] = ov1;
            }
        }
    }
}

// ---------------- launch ----------------
extern "C" void kernel_launch(void* const* d_in, const int* in_sizes, int n_in,
                              void* d_out, int out_size)
{
    const float* x      = (const float*)d_in[0];
    const float* wq     = (const float*)d_in[1];
    const float* wk     = (const float*)d_in[2];
    const float* wv     = (const float*)d_in[3];
    const float* wproj  = (const float*)d_in[4];
    const float* bproj  = (const float*)d_in[5];
    const float* gq     = (const float*)d_in[6];
    const float* gk     = (const float*)d_in[7];
    const float* gv     = (const float*)d_in[8];
    const float* gvm    = (const float*)d_in[9];
    const float* gmlp   = (const float*)d_in[10];
    const float* m_in_w = (const float*)d_in[11];
    const float* m_cw   = (const float*)d_in[12];
    const float* m_cb   = (const float*)d_in[13];
    const float* m_xp   = (const float*)d_in[14];
    const float* m_dtw  = (const float*)d_in[15];
    const float* m_dtb  = (const float*)d_in[16];
    const float* m_Alog = (const float*)d_in[17];
    const float* m_D    = (const float*)d_in[18];
    const float* m_outw = (const float*)d_in[19];
    const float* se_w1  = (const float*)d_in[20];
    const float* se_b1  = (const float*)d_in[21];
    const float* se_w2  = (const float*)d_in[22];
    const float* se_b2  = (const float*)d_in[23];
    const float* mlp_w1 = (const float*)d_in[24];
    const float* mlp_b1 = (const float*)d_in[25];
    const float* mlp_w2 = (const float*)d_in[26];
    const float* mlp_b2 = (const float*)d_in[27];
    const float* gamma1 = (const float*)d_in[28];
    const float* gamma2 = (const float*)d_in[29];
    float* out = (float*)d_out;

    void *p_wqkvbf, *p_wprojbf, *p_winbf, *p_wxbf, *p_woutbf;
    void *p_xn1bf, *p_xn64bf, *p_attnobf, *p_xmbf, *p_ymgbf;
    void *p_qkvbf, *p_tmpbf, *p_pjbf, *p_ybf;
    cudaGetSymbolAddress(&p_wqkvbf, g_wqkvbf);
    cudaGetSymbolAddress(&p_wprojbf, g_wprojbf);
    cudaGetSymbolAddress(&p_winbf, g_winbf);
    cudaGetSymbolAddress(&p_wxbf, g_wxbf);
    cudaGetSymbolAddress(&p_woutbf, g_woutbf);
    cudaGetSymbolAddress(&p_xn1bf, g_xn1bf);
    cudaGetSymbolAddress(&p_xn64bf, g_xn64bf);
    cudaGetSymbolAddress(&p_attnobf, g_attnobf);
    cudaGetSymbolAddress(&p_xmbf, g_xmbf);
    cudaGetSymbolAddress(&p_ymgbf, g_ymgbf);
    cudaGetSymbolAddress(&p_qkvbf, g_qkvbf);
    cudaGetSymbolAddress(&p_tmpbf, g_tmpbf);
    cudaGetSymbolAddress(&p_pjbf, g_pjbf);
    cudaGetSymbolAddress(&p_ybf, g_ybf);

    int mlpf_smem = (128*136 + 64*136 + 64*136 + 128*72)*2;
    cudaFuncSetAttribute(mma_mlpfused_kernel,
        cudaFuncAttributeMaxDynamicSharedMemorySize, mlpf_smem);

    cudaStream_t s1;
    cudaStreamCreateWithFlags(&s1, cudaStreamNonBlocking);
    cudaEvent_t evFork, evF, evJ, evW;
    cudaEventCreateWithFlags(&evFork, cudaEventDisableTiming);
    cudaEventCreateWithFlags(&evF, cudaEventDisableTiming);
    cudaEventCreateWithFlags(&evJ, cudaEventDisableTiming);
    cudaEventCreateWithFlags(&evW, cudaEventDisableTiming);

    // fork s1 from the capture-origin stream FIRST (required for graph capture)
    cudaEventRecord(evFork, 0);
    cudaStreamWaitEvent(s1, evFork, 0);

    // wprep on s1, concurrent with rms1 on default stream
    wprep_kernel<<<256, 256, 0, s1>>>(mlp_w1, mlp_w2, m_xp, wq, wk, wv, gq, gk, gv,
                                      wproj, m_in_w, m_outw);
    cudaEventRecord(evW, s1);
    rms1_kernel<<<784, 256>>>(x, gvm);

    cudaEventRecord(evF, 0);
    cudaStreamWaitEvent(s1, evF, 0);
    cudaStreamWaitEvent(0, evW, 0);   // mamba-branch GEMMs need bf16 weights

    // attention branch on s1 (after wprep + rms1)
    mma_gemm_kernel<64><<<dim3(25, 3, 16), 256, 0, s1>>>(
        (const __nv_bfloat16*)p_wqkvbf, (const __nv_bfloat16*)p_xn1bf,
        (__nv_bfloat16*)p_qkvbf, nullptr, 192, 192, 0);
    attncore_kernel<<<1024, 256, 0, s1>>>();
    mma_gemm_kernel<64><<<dim3(25, 1, 16), 256, 0, s1>>>(
        (const __nv_bfloat16*)p_wprojbf, (const __nv_bfloat16*)p_attnobf,
        (__nv_bfloat16*)p_ybf, bproj, 64, 128, 0);
    cudaEventRecord(evJ, s1);

    // mamba branch on default stream
    mma_gemm_kernel<64><<<dim3(25, 2, 16), 256>>>(
        (const __nv_bfloat16*)p_winbf, (const __nv_bfloat16*)p_xn64bf,
        (__nv_bfloat16*)p_tmpbf, nullptr, 128, 128, 0);
    dwconvT_kernel<<<2048, 256>>>(m_cw, m_cb);
    mma_gemm_kernel<128><<<dim3(25, 3, 16), 256>>>(
        (const __nv_bfloat16*)p_wxbf, (const __nv_bfloat16*)p_xmbf,
        (__nv_bfloat16*)p_pjbf, nullptr, 144, 144, 0);
    transposePJ_kernel<<<1152, 256>>>();
    scan_kernel<<<256, 128>>>(m_dtw, m_dtb, m_Alog, m_D);
    mergegelu_kernel<<<dim3(128, 16), 256>>>();
    mma_gemm_kernel<128><<<dim3(25, 1, 16), 256>>>(
        (const __nv_bfloat16*)p_woutbf, (const __nv_bfloat16*)p_ymgbf,
        (__nv_bfloat16*)p_ybf, nullptr, 64, 128, 64);

    // join attention branch before pool
    cudaStreamWaitEvent(0, evJ, 0);

    pool_kernel<<<BBATCH*DIMC, 256>>>();
    se_kernel<<<BBATCH, 128>>>(se_w1, se_b1, se_w2, se_b2);
    residrms_kernel<<<784, 256>>>(x, gamma1, gmlp);

    mma_mlpfused_kernel<<<dim3(25, 16), 256, mlpf_smem>>>(mlp_b1, mlp_b2, gamma1, gamma2, x, out);
}